// round 10
// baseline (speedup 1.0000x reference)
#include <cuda_runtime.h>
#include <cuda_bf16.h>
#include <cstdint>

#define D  768
#define KP 256

__device__ __align__(16) uint8_t       g_pn8[KP * D];   // normalized prototypes e4m3 [k][d]
__device__ __align__(16) __nv_bfloat16 g_pwt[D * KP];   // (P @ W^T / 256) : [e][k] bf16

// ---------------------------------------------------------------------------
__device__ __forceinline__ uint32_t smem_u32(const void* p) {
    uint32_t a;
    asm("{ .reg .u64 t; cvta.to.shared.u64 t, %1; cvt.u32.u64 %0, t; }" : "=r"(a) : "l"(p));
    return a;
}
__device__ __forceinline__ uint32_t packbf(float lo, float hi) {
    __nv_bfloat162 h = __float22bfloat162_rn(make_float2(lo, hi));
    return *reinterpret_cast<uint32_t*>(&h);
}
__device__ __forceinline__ uint16_t packe4m3(float lo, float hi) {
    uint16_t h;
    asm("cvt.rn.satfinite.e4m3x2.f32 %0, %1, %2;" : "=h"(h) : "f"(hi), "f"(lo));
    return h;
}
__device__ __forceinline__ void ldsm_x4(uint32_t& r0, uint32_t& r1, uint32_t& r2, uint32_t& r3,
                                        uint32_t addr) {
    asm volatile("ldmatrix.sync.aligned.m8n8.x4.shared.b16 {%0,%1,%2,%3}, [%4];"
                 : "=r"(r0), "=r"(r1), "=r"(r2), "=r"(r3) : "r"(addr));
}
__device__ __forceinline__ void mma4(float* c, uint32_t a0, uint32_t a1, uint32_t a2, uint32_t a3,
                                     uint32_t b0, uint32_t b1) {
    asm volatile(
        "mma.sync.aligned.m16n8k16.row.col.f32.bf16.bf16.f32 "
        "{%0,%1,%2,%3}, {%4,%5,%6,%7}, {%8,%9}, {%0,%1,%2,%3};"
        : "+f"(c[0]), "+f"(c[1]), "+f"(c[2]), "+f"(c[3])
        : "r"(a0), "r"(a1), "r"(a2), "r"(a3), "r"(b0), "r"(b1));
}
__device__ __forceinline__ void mma8(float* c, uint32_t a0, uint32_t a1, uint32_t a2, uint32_t a3,
                                     uint32_t b0, uint32_t b1) {
    asm volatile(
        "mma.sync.aligned.m16n8k32.row.col.f32.e4m3.e4m3.f32 "
        "{%0,%1,%2,%3}, {%4,%5,%6,%7}, {%8,%9}, {%0,%1,%2,%3};"
        : "+f"(c[0]), "+f"(c[1]), "+f"(c[2]), "+f"(c[3])
        : "r"(a0), "r"(a1), "r"(a2), "r"(a3), "r"(b0), "r"(b1));
}
#define CP16(dst, src) asm volatile("cp.async.cg.shared.global [%0], [%1], 16;" :: "r"(dst), "l"(src))
#define CP_COMMIT()    asm volatile("cp.async.commit_group;" ::: "memory")
#define CP_WAIT0()     asm volatile("cp.async.wait_group 0;" ::: "memory")

// ---------------------------------------------------------------------------
// Merged prep kernel: blocks [0,256) normalize prototypes -> e4m3; rest build PWT (bf16)
// ---------------------------------------------------------------------------
__global__ void prep_kernel(const float* __restrict__ P, const float* __restrict__ W) {
    __shared__ float Pt[256 * 33 + 8];
    __shared__ float Wt[4 * 33];
    if (blockIdx.x < 256) {
        float* red = Pt;
        int k = blockIdx.x;
        const float* row = P + k * D;
        float s = 0.f;
        for (int d = threadIdx.x; d < D; d += 256) { float v = row[d]; s += v * v; }
#pragma unroll
        for (int o = 16; o; o >>= 1) s += __shfl_xor_sync(0xffffffffu, s, o);
        if ((threadIdx.x & 31) == 0) red[threadIdx.x >> 5] = s;
        __syncthreads();
        if (threadIdx.x == 0) {
            float t = 0.f;
#pragma unroll
            for (int i = 0; i < 8; ++i) t += red[i];
            red[0] = 1.f / fmaxf(sqrtf(t), 1e-12f);
        }
        __syncthreads();
        float iv = red[0];
        for (int p = threadIdx.x; p < D / 2; p += 256) {
            uint16_t h = packe4m3(row[2 * p] * iv, row[2 * p + 1] * iv);
            *reinterpret_cast<uint16_t*>(g_pn8 + k * D + 2 * p) = h;
        }
    } else {
        int e0 = (blockIdx.x - 256) * 4;
        int k  = threadIdx.x;
        float a0 = 0.f, a1 = 0.f, a2 = 0.f, a3 = 0.f;
        for (int dc = 0; dc < D; dc += 32) {
#pragma unroll
            for (int it = 0; it < 32; ++it) {
                int idx = threadIdx.x + 256 * it;
                int row = idx >> 5, d = idx & 31;
                Pt[row * 33 + d] = P[row * D + dc + d];
            }
            if (threadIdx.x < 128) {
                int e = threadIdx.x >> 5, d = threadIdx.x & 31;
                Wt[e * 33 + d] = W[(e0 + e) * D + dc + d];
            }
            __syncthreads();
#pragma unroll
            for (int d = 0; d < 32; ++d) {
                float p = Pt[k * 33 + d];
                a0 += p * Wt[0 * 33 + d];
                a1 += p * Wt[1 * 33 + d];
                a2 += p * Wt[2 * 33 + d];
                a3 += p * Wt[3 * 33 + d];
            }
            __syncthreads();
        }
        const float sc = 1.f / 256.f;
        g_pwt[(e0 + 0) * KP + k] = __float2bfloat16(a0 * sc);
        g_pwt[(e0 + 1) * KP + k] = __float2bfloat16(a1 * sc);
        g_pwt[(e0 + 2) * KP + k] = __float2bfloat16(a2 * sc);
        g_pwt[(e0 + 3) * KP + k] = __float2bfloat16(a3 * sc);
    }
}

// ---------------------------------------------------------------------------
// Main fused kernel: M_TILE=64, 256 threads, 2 CTAs/SM
//   Phase 1: FP8, K-chunks of 128 (6 iters, staging hidden under MMA)
//   Phase 3: bf16, 64-col chunks double-buffered (cp overlaps MMA)
// ---------------------------------------------------------------------------
#define OFF_INV   0            // float[64]
#define OFF_INVS  256          // float[64]
#define OFF_PARTS 512          // float[4][64]
#define OFF_EXP   1536         // bf16 [64][264] (stride 528B) = 33792
#define OFF_PW0   35328        // bf16 [64][264] = 33792
#define OFF_PW1   69120        // bf16 [64][264] = 33792
#define SMEM_MAIN 102912
// phase-1 overlays (e4m3, stride 144B = 9 odd 16B units):
#define OFF_XB0   1536                 // e4m3 [64][144]  = 9216
#define OFF_XB1   (1536 + 9216)
#define OFF_PN0   (1536 + 18432)       // e4m3 [256][144] = 36864
#define OFF_PN1   (1536 + 55296)       // ends 93696

__global__ __launch_bounds__(256, 2)
void main_kernel(const float* __restrict__ x, const float* __restrict__ bias,
                 float* __restrict__ out) {
    extern __shared__ char smem[];
    const uint32_t sb = smem_u32(smem);
    const int tid = threadIdx.x, w = tid >> 5, lane = tid & 31;
    const int g = lane >> 2, q = lane & 3;
    const long m0 = (long)blockIdx.x * 64;

    float* inv   = reinterpret_cast<float*>(smem + OFF_INV);
    float* invS  = reinterpret_cast<float*>(smem + OFF_INVS);
    float* parts = reinterpret_cast<float*>(smem + OFF_PARTS);

    // ---- phase-1 tiling: wm1 = M half (32 rows), wn1 = N group (64 cols) ----
    const int wm1 = w & 1, wn1 = w >> 1;
    // x staging: warp w covers rows {w, w+8, ..., w+56}; lane = col-quad 0..31
    const int c4 = lane;
    const float* xbase = x + (m0 + w) * D + c4 * 4;
    const uint32_t aoff1 = (wm1 * 32 + (lane & 7) + ((lane >> 3) & 1) * 8) * 144 + ((lane >> 4) & 1) * 16;
    const uint32_t boff1 = (wn1 * 64 + (lane & 7) + ((lane >> 4) & 1) * 8) * 144 + ((lane >> 3) & 1) * 16;
    // pn cp.async decomposition: 2048 16B units per 128-col chunk
    const int pnr = tid >> 3, pnu = tid & 7;   // row base (+32/it), unit

    float acc[2][8][4];
#pragma unroll
    for (int mt = 0; mt < 2; ++mt)
#pragma unroll
        for (int nt = 0; nt < 8; ++nt)
#pragma unroll
            for (int j = 0; j < 4; ++j) acc[mt][nt][j] = 0.f;

    float sq[8] = {0.f, 0.f, 0.f, 0.f, 0.f, 0.f, 0.f, 0.f};
    float4 R[8];

    // ---- prologue: load + stage x chunk 0, cp.async pn chunk 0 ----
#pragma unroll
    for (int f = 0; f < 8; ++f)
        R[f] = *reinterpret_cast<const float4*>(xbase + f * 8 * D);
#pragma unroll
    for (int f = 0; f < 8; ++f) {
        float4 v = R[f];
        sq[f] += v.x * v.x + v.y * v.y + v.z * v.z + v.w * v.w;
        uint32_t word = (uint32_t)packe4m3(v.x, v.y) | ((uint32_t)packe4m3(v.z, v.w) << 16);
        *reinterpret_cast<uint32_t*>(smem + OFF_XB0 + (w + 8 * f) * 144 + c4 * 4) = word;
    }
#pragma unroll
    for (int it = 0; it < 8; ++it) {
        int row = pnr + 32 * it;
        CP16(sb + OFF_PN0 + row * 144 + pnu * 16, g_pn8 + row * D + pnu * 16);
    }
    CP_COMMIT();

    // ---- Phase 1 (FP8): sim[64][256] = x @ pn^T (6 K-chunks of 128) ----
    for (int c = 0; c < 6; ++c) {
        const int b = c & 1;
        const uint32_t XB = b ? (sb + OFF_XB1) : (sb + OFF_XB0);
        const uint32_t PN = b ? (sb + OFF_PN1) : (sb + OFF_PN0);
        CP_WAIT0();
        __syncthreads();            // PN(c) + XB(c) ready; buffers b^1 free
        if (c < 5) {
            const uint32_t PNn = b ? (sb + OFF_PN0) : (sb + OFF_PN1);
#pragma unroll
            for (int it = 0; it < 8; ++it) {
                int row = pnr + 32 * it;
                CP16(PNn + row * 144 + pnu * 16, g_pn8 + row * D + (c + 1) * 128 + pnu * 16);
            }
            CP_COMMIT();
            // issue next x loads now; latency hidden under MMA below
#pragma unroll
            for (int f = 0; f < 8; ++f)
                R[f] = *reinterpret_cast<const float4*>(xbase + f * 8 * D + (c + 1) * 128);
        }
        // MMA(c): 4 k32-steps
#pragma unroll
        for (int ks = 0; ks < 4; ++ks) {
            uint32_t a0[2], a1[2], a2[2], a3[2];
#pragma unroll
            for (int mt = 0; mt < 2; ++mt)
                ldsm_x4(a0[mt], a1[mt], a2[mt], a3[mt], XB + aoff1 + mt * 16 * 144 + ks * 32);
#pragma unroll
            for (int p = 0; p < 4; ++p) {
                uint32_t b0, b1, b2, b3;
                ldsm_x4(b0, b1, b2, b3, PN + boff1 + p * 16 * 144 + ks * 32);
#pragma unroll
                for (int mt = 0; mt < 2; ++mt) {
                    mma8(acc[mt][2 * p],     a0[mt], a1[mt], a2[mt], a3[mt], b0, b1);
                    mma8(acc[mt][2 * p + 1], a0[mt], a1[mt], a2[mt], a3[mt], b2, b3);
                }
            }
        }
        if (c < 5) {
            const uint32_t XBn = b ? (sb + OFF_XB0 - sb) + sb : (sb + OFF_XB1);
            const uint32_t xoff = (b ? OFF_XB0 : OFF_XB1);
#pragma unroll
            for (int f = 0; f < 8; ++f) {
                float4 v = R[f];
                sq[f] += v.x * v.x + v.y * v.y + v.z * v.z + v.w * v.w;
                uint32_t word = (uint32_t)packe4m3(v.x, v.y) | ((uint32_t)packe4m3(v.z, v.w) << 16);
                *reinterpret_cast<uint32_t*>(smem + xoff + (w + 8 * f) * 144 + c4 * 4) = word;
            }
        }
    }
    // ---- row-norm reduce (all chunks' sq accumulated) ----
#pragma unroll
    for (int f = 0; f < 8; ++f) {
        float s = sq[f];
#pragma unroll
        for (int o = 16; o; o >>= 1) s += __shfl_xor_sync(0xffffffffu, s, o);
        if (lane == 0) inv[w + 8 * f] = 1.f / fmaxf(sqrtf(s), 1e-12f);
    }
    __syncthreads();   // phase-1 reads done; inv visible; overlay reusable

    // ---- kick off PW chunk 0 staging (overlaps softmax) ----
#pragma unroll
    for (int it = 0; it < 8; ++it) {
        int idx = tid + 256 * it;           // 0..2047 16B units
        int row = idx >> 5, u = idx & 31;   // 64 rows x 32 units
        CP16(sb + OFF_PW0 + row * 528 + u * 16,
             reinterpret_cast<const char*>(g_pwt) + row * 512 + u * 16);
    }
    CP_COMMIT();

    // ---- softmax: scale by inv[row], exp, write bf16 exp tile + partial sums ----
#pragma unroll
    for (int mt = 0; mt < 2; ++mt) {
        const int r0 = wm1 * 32 + mt * 16 + g, r1 = r0 + 8;
        const float iv0 = inv[r0], iv1 = inv[r1];
        float s0 = 0.f, s1 = 0.f;
#pragma unroll
        for (int nt = 0; nt < 8; ++nt) {
            float e0 = __expf(acc[mt][nt][0] * iv0);
            float e1 = __expf(acc[mt][nt][1] * iv0);
            float e2 = __expf(acc[mt][nt][2] * iv1);
            float e3 = __expf(acc[mt][nt][3] * iv1);
            const uint32_t cb = (wn1 * 64 + nt * 8 + 2 * q) * 2;
            *reinterpret_cast<uint32_t*>(smem + OFF_EXP + r0 * 528 + cb) = packbf(e0, e1);
            *reinterpret_cast<uint32_t*>(smem + OFF_EXP + r1 * 528 + cb) = packbf(e2, e3);
            s0 += e0 + e1; s1 += e2 + e3;
        }
        s0 += __shfl_xor_sync(0xffffffffu, s0, 1);
        s0 += __shfl_xor_sync(0xffffffffu, s0, 2);
        s1 += __shfl_xor_sync(0xffffffffu, s1, 1);
        s1 += __shfl_xor_sync(0xffffffffu, s1, 2);
        if (q == 0) { parts[wn1 * 64 + r0] = s0; parts[wn1 * 64 + r1] = s1; }
    }
    __syncthreads();
    if (tid < 64) {
        float s = parts[tid] + parts[64 + tid] + parts[128 + tid] + parts[192 + tid];
        invS[tid] = 1.f / s;
    }

    // ---- Phase 3 (bf16): out[64][768] = exp @ PWT^T (12 chunks of 64 cols, dbl-buf) ----
    const int wm3 = w & 1, wn3 = w >> 1;      // 2 M groups (32 rows) x 4 N groups (16 cols)
    const uint32_t aoff3 = (wm3 * 32 + (lane & 7) + ((lane >> 3) & 1) * 8) * 528 + ((lane >> 4) & 1) * 16;
    const uint32_t boff3 = (wn3 * 16 + (lane & 7) + ((lane >> 4) & 1) * 8) * 528 + ((lane >> 3) & 1) * 16;

    for (int j = 0; j < 12; ++j) {
        const uint32_t PW = (j & 1) ? (sb + OFF_PW1) : (sb + OFF_PW0);
        CP_WAIT0();
        __syncthreads();                      // PW(j) ready; buffer j^1 free; invS visible
        if (j < 11) {
            const uint32_t PWn = (j & 1) ? (sb + OFF_PW0) : (sb + OFF_PW1);
#pragma unroll
            for (int it = 0; it < 8; ++it) {
                int idx = tid + 256 * it;
                int row = idx >> 5, u = idx & 31;
                CP16(PWn + row * 528 + u * 16,
                     reinterpret_cast<const char*>(g_pwt) + ((j + 1) * 64 + row) * 512 + u * 16);
            }
            CP_COMMIT();
        }
        float acc2[2][2][4];
#pragma unroll
        for (int mt = 0; mt < 2; ++mt)
#pragma unroll
            for (int nt = 0; nt < 2; ++nt)
#pragma unroll
                for (int jj = 0; jj < 4; ++jj) acc2[mt][nt][jj] = 0.f;

#pragma unroll
        for (int ks = 0; ks < 16; ++ks) {
            uint32_t b0, b1, b2, b3;
            ldsm_x4(b0, b1, b2, b3, PW + boff3 + ks * 32);
#pragma unroll
            for (int mt = 0; mt < 2; ++mt) {
                uint32_t a0, a1, a2, a3;
                ldsm_x4(a0, a1, a2, a3, sb + OFF_EXP + aoff3 + mt * 16 * 528 + ks * 32);
                mma4(acc2[mt][0], a0, a1, a2, a3, b0, b1);
                mma4(acc2[mt][1], a0, a1, a2, a3, b2, b3);
            }
        }
        // epilogue (overlaps the in-flight cp for j+1)
#pragma unroll
        for (int mt = 0; mt < 2; ++mt) {
            const int r0 = wm3 * 32 + mt * 16 + g, r1 = r0 + 8;
            const float is0 = invS[r0], is1 = invS[r1];
#pragma unroll
            for (int nt = 0; nt < 2; ++nt) {
                const int cc = j * 64 + wn3 * 16 + nt * 8 + 2 * q;
                const float2 bv = *reinterpret_cast<const float2*>(bias + cc);
                *reinterpret_cast<float2*>(out + (m0 + r0) * D + cc) =
                    make_float2(acc2[mt][nt][0] * is0 + bv.x, acc2[mt][nt][1] * is0 + bv.y);
                *reinterpret_cast<float2*>(out + (m0 + r1) * D + cc) =
                    make_float2(acc2[mt][nt][2] * is1 + bv.x, acc2[mt][nt][3] * is1 + bv.y);
            }
        }
    }
}

// ---------------------------------------------------------------------------
extern "C" void kernel_launch(void* const* d_in, const int* in_sizes, int n_in,
                              void* d_out, int out_size) {
    const float* x = (const float*)d_in[0];
    const float* P = (const float*)d_in[1];
    const float* W = (const float*)d_in[2];
    const float* b = (const float*)d_in[3];
    float* out = (float*)d_out;

    cudaFuncSetAttribute(main_kernel, cudaFuncAttributeMaxDynamicSharedMemorySize, SMEM_MAIN);

    prep_kernel<<<448, 256>>>(P, W);

    int rows = in_sizes[0] / D;               // 131072
    main_kernel<<<rows / 64, 256, SMEM_MAIN>>>(x, b, out);
}